// round 1
// baseline (speedup 1.0000x reference)
#include <cuda_runtime.h>
#include <cuda_bf16.h>
#include <math.h>

#define S_    1024
#define EMB_  1024
#define M_    6
#define A_    4
#define QH_   2
#define D_    128
#define E_    (S_*A_)

// ---------------- scratch (static device globals; no allocation) ----------------
__device__ float g_yq[S_*M_*QH_*D_];     // 1024 x 1536
__device__ float g_yk[S_*M_*D_];         // 1024 x 768
__device__ float g_yv[S_*M_*D_];         // 1024 x 768
__device__ float g_probs[S_*M_];
__device__ float g_ent[S_];
__device__ int   g_primary[S_];
__device__ int   g_kvidx[E_];            // group id per flattened entry e = t*4+a
__device__ float g_kvw[E_];
__device__ int   g_rank[E_];
__device__ int   g_list[M_*E_];          // per-expert sorted entry list (stride E_)
__device__ int   g_counts[M_];
__device__ float g_qsrt[M_*E_*QH_*D_];   // per-expert RoPE'd Q, dense by rank
__device__ float g_ksrt[M_*E_*D_];
__device__ float g_vsrt[M_*E_*D_];
__device__ float g_ao[S_*A_*QH_*D_];     // 1024 x 1024 pre-output

// ---------------- router: logits, softmax, top-k, weights, aux terms ----------------
__global__ void router_kernel(const float* __restrict__ x, const float* __restrict__ wr) {
    int gw   = (blockIdx.x * blockDim.x + threadIdx.x) >> 5;   // token
    int lane = threadIdx.x & 31;
    if (gw >= S_) return;
    const float* xr = x + gw * EMB_;
    float acc[M_];
#pragma unroll
    for (int m = 0; m < M_; m++) acc[m] = 0.f;
    for (int i = lane; i < EMB_; i += 32) {
        float xv = xr[i];
#pragma unroll
        for (int m = 0; m < M_; m++) acc[m] += xv * wr[m*EMB_ + i];
    }
#pragma unroll
    for (int m = 0; m < M_; m++)
        for (int o = 16; o; o >>= 1) acc[m] += __shfl_xor_sync(0xffffffffu, acc[m], o);
    if (lane == 0) {
        float mx = acc[0];
#pragma unroll
        for (int m = 1; m < M_; m++) mx = fmaxf(mx, acc[m]);
        float ex[M_], ssum = 0.f;
#pragma unroll
        for (int m = 0; m < M_; m++) { ex[m] = expf(acc[m] - mx); ssum += ex[m]; }
        float inv = 1.f / ssum;
        float ent = 0.f;
#pragma unroll
        for (int m = 0; m < M_; m++) {
            float p = ex[m] * inv;
            g_probs[gw*M_ + m] = p;
            ent -= p * logf(p + 1e-8f);
        }
        g_ent[gw] = ent;
        // top-4 of 6, descending, stable (strict > keeps lowest index on ties)
        float v[M_];
#pragma unroll
        for (int m = 0; m < M_; m++) v[m] = acc[m];
        int   idx[A_]; float tv[A_];
#pragma unroll
        for (int a = 0; a < A_; a++) {
            float best = -INFINITY; int bi = 0;
#pragma unroll
            for (int m = 0; m < M_; m++) if (v[m] > best) { best = v[m]; bi = m; }
            idx[a] = bi; tv[a] = best; v[bi] = -INFINITY;
        }
        float wv[A_], ws = 0.f;
#pragma unroll
        for (int a = 0; a < A_; a++) { wv[a] = expf(tv[a] - tv[0]); ws += wv[a]; }
        float winv = 1.f / ws;
#pragma unroll
        for (int a = 0; a < A_; a++) {
            g_kvidx[gw*A_ + a] = idx[a];
            g_kvw  [gw*A_ + a] = wv[a] * winv;
        }
        g_primary[gw] = idx[0];
    }
}

// ---------------- build per-expert lists + ranks (order = flattened e) ----------------
__global__ void build_lists_kernel() {
    __shared__ int sg[E_];
    for (int i = threadIdx.x; i < E_; i += blockDim.x) sg[i] = g_kvidx[i];
    __syncthreads();
    int m = threadIdx.x;
    if (m < M_) {
        int c = 0;
        for (int e = 0; e < E_; e++) {
            if (sg[e] == m) { g_rank[e] = c; g_list[m*E_ + c] = e; c++; }
        }
        g_counts[m] = c;
    }
}

// ---------------- deterministic aux-loss reduction ----------------
__global__ void aux_reduce_kernel(float* __restrict__ d_out, int out_size) {
    __shared__ float red[256];
    __shared__ float tot[13];
    int tid = threadIdx.x;
    float pf[M_], pp[M_], pe = 0.f;
#pragma unroll
    for (int m = 0; m < M_; m++) { pf[m] = 0.f; pp[m] = 0.f; }
    for (int t = tid; t < S_; t += 256) {
        int pm = g_primary[t];
        pe += g_ent[t];
#pragma unroll
        for (int m = 0; m < M_; m++) {
            pp[m] += g_probs[t*M_ + m];
            pf[m] += (pm == m) ? 1.f : 0.f;
        }
    }
    for (int q = 0; q < 13; q++) {
        float v = (q < 6) ? pf[q] : (q < 12 ? pp[q-6] : pe);
        red[tid] = v; __syncthreads();
        for (int s = 128; s > 0; s >>= 1) {
            if (tid < s) red[tid] += red[tid + s];
            __syncthreads();
        }
        if (tid == 0) tot[q] = red[0];
        __syncthreads();
    }
    if (tid == 0) {
        float bal = 0.f;
#pragma unroll
        for (int m = 0; m < M_; m++) bal += (tot[m] / (float)S_) * (tot[6+m] / (float)S_);
        bal *= (float)M_;
        float aux = 0.01f * bal - 0.01f * (tot[12] / (float)S_);
        d_out[out_size - 1] = aux;
    }
}

// ---------------- SGEMM: C[MxN] = A[MxK] * B[NxK]^T (row-major, M%128==N%128==0, K%8==0) ----------------
__global__ __launch_bounds__(256) void sgemm_tn(
    const float* __restrict__ A, const float* __restrict__ B, float* __restrict__ C,
    int M, int N, int K)
{
    __shared__ float As[8][128];
    __shared__ float Bs[8][128];
    int tid  = threadIdx.x;
    const float* Ab = A + (size_t)blockIdx.y * 128 * K;
    const float* Bb = B + (size_t)blockIdx.x * 128 * K;
    int lrow = tid >> 1;
    int lk   = (tid & 1) * 4;
    int ty   = tid >> 4, tx = tid & 15;
    float acc[8][8];
#pragma unroll
    for (int i = 0; i < 8; i++)
#pragma unroll
        for (int j = 0; j < 8; j++) acc[i][j] = 0.f;

    for (int k0 = 0; k0 < K; k0 += 8) {
        float4 av = *(const float4*)(Ab + (size_t)lrow * K + k0 + lk);
        float4 bv = *(const float4*)(Bb + (size_t)lrow * K + k0 + lk);
        __syncthreads();
        As[lk+0][lrow] = av.x; As[lk+1][lrow] = av.y; As[lk+2][lrow] = av.z; As[lk+3][lrow] = av.w;
        Bs[lk+0][lrow] = bv.x; Bs[lk+1][lrow] = bv.y; Bs[lk+2][lrow] = bv.z; Bs[lk+3][lrow] = bv.w;
        __syncthreads();
#pragma unroll
        for (int k = 0; k < 8; k++) {
            float a[8], b[8];
            *(float4*)&a[0] = *(const float4*)&As[k][ty*8];
            *(float4*)&a[4] = *(const float4*)&As[k][ty*8 + 4];
            *(float4*)&b[0] = *(const float4*)&Bs[k][tx*8];
            *(float4*)&b[4] = *(const float4*)&Bs[k][tx*8 + 4];
#pragma unroll
            for (int i = 0; i < 8; i++)
#pragma unroll
                for (int j = 0; j < 8; j++) acc[i][j] += a[i] * b[j];
        }
    }
    float* Cp = C + (size_t)(blockIdx.y*128 + ty*8) * N + blockIdx.x*128 + tx*8;
#pragma unroll
    for (int i = 0; i < 8; i++) {
        *(float4*)(Cp + (size_t)i * N)     = *(float4*)&acc[i][0];
        *(float4*)(Cp + (size_t)i * N + 4) = *(float4*)&acc[i][4];
    }
}

// ---------------- gather selected experts + RoPE (pos = rank) ----------------
__global__ void gather_rope_kernel() {
    int e = blockIdx.x;
    int d = threadIdx.x;
    int m = g_kvidx[e];
    int r = g_rank[e];
    int t = e >> 2;
    int dm = d & 63;
    float invf = expf(-(float)dm * (9.210340371976184f / 64.0f)); // 10000^(-dm/64)
    float fr = (float)r * invf;
    float sn, cs;
    sincosf(fr, &sn, &cs);
    int   partner = (d < 64) ? d + 64 : d - 64;
    float sgn     = (d < 64) ? -1.f : 1.f;
    int ro = m * E_ + r;
    const float* kb = g_yk + t * (M_ * D_) + m * D_;
    g_ksrt[ro*D_ + d] = kb[d] * cs + sgn * kb[partner] * sn;
    g_vsrt[ro*D_ + d] = g_yv[t*(M_*D_) + m*D_ + d];
#pragma unroll
    for (int h = 0; h < QH_; h++) {
        const float* qb = g_yq + t * (M_*QH_*D_) + (m*QH_ + h) * D_;
        g_qsrt[(ro*QH_ + h)*D_ + d] = qb[d] * cs + sgn * qb[partner] * sn;
    }
}

// ---------------- flash attention per (expert, head, q-tile) ----------------
#define TQ 32
#define TK 32
__global__ __launch_bounds__(256) void attn_kernel() {
    int m = blockIdx.z, h = blockIdx.y;
    int L = g_counts[m];
    int q0 = blockIdx.x * TQ;
    if (q0 >= L) return;

    __shared__ float Qs[TQ * 128];
    __shared__ float KV[128 * 33];   // K transposed [d][j] w/ pad; reused as V [j][d]

    int tid = threadIdx.x, w = tid >> 5, lane = tid & 31;
    int row0 = w * 4;

    for (int idx = tid; idx < TQ*128; idx += 256) {
        int i = idx >> 7, d = idx & 127;
        int r = q0 + i;
        Qs[idx] = (r < L) ? g_qsrt[((m*E_ + r)*QH_ + h)*D_ + d] : 0.f;
    }

    float O[4][4];
#pragma unroll
    for (int i = 0; i < 4; i++)
#pragma unroll
        for (int c = 0; c < 4; c++) O[i][c] = 0.f;
    float mr[4] = {-INFINITY, -INFINITY, -INFINITY, -INFINITY};
    float lr[4] = {0.f, 0.f, 0.f, 0.f};
    const float scale = 0.08838834764831845f; // 1/sqrt(128)

    for (int kt = 0; kt < L; kt += TK) {
        __syncthreads();   // previous V reads (and initial Q fill) complete
        for (int idx = tid; idx < TK*128; idx += 256) {
            int j = idx >> 7, d = idx & 127;
            int kk = kt + j;
            KV[d*33 + j] = (kk < L) ? g_ksrt[(m*E_ + kk)*D_ + d] : 0.f;
        }
        __syncthreads();

        float s[4] = {0.f, 0.f, 0.f, 0.f};
#pragma unroll 4
        for (int d = 0; d < 128; d++) {
            float kv = KV[d*33 + lane];
            s[0] += Qs[(row0+0)*128 + d] * kv;
            s[1] += Qs[(row0+1)*128 + d] * kv;
            s[2] += Qs[(row0+2)*128 + d] * kv;
            s[3] += Qs[(row0+3)*128 + d] * kv;
        }
        bool kvalid = (kt + lane) < L;
        float p[4];
#pragma unroll
        for (int i = 0; i < 4; i++) {
            float sv = kvalid ? s[i] * scale : -1e30f;
            float smax = sv;
            for (int o = 16; o; o >>= 1) smax = fmaxf(smax, __shfl_xor_sync(0xffffffffu, smax, o));
            float nm = fmaxf(mr[i], smax);
            p[i] = expf(sv - nm);
            float corr = expf(mr[i] - nm);
            float ps = p[i];
            for (int o = 16; o; o >>= 1) ps += __shfl_xor_sync(0xffffffffu, ps, o);
            lr[i] = lr[i] * corr + ps;
#pragma unroll
            for (int c = 0; c < 4; c++) O[i][c] *= corr;
            mr[i] = nm;
        }

        __syncthreads();   // all warps done reading K
        for (int idx = tid; idx < TK*128; idx += 256) {
            int j = idx >> 7, d = idx & 127;
            int kk = kt + j;
            KV[j*128 + d] = (kk < L) ? g_vsrt[(m*E_ + kk)*D_ + d] : 0.f;
        }
        __syncthreads();

#pragma unroll 4
        for (int j = 0; j < 32; j++) {
            float v0 = KV[j*128 + lane];
            float v1 = KV[j*128 + lane + 32];
            float v2 = KV[j*128 + lane + 64];
            float v3 = KV[j*128 + lane + 96];
#pragma unroll
            for (int i = 0; i < 4; i++) {
                float pj = __shfl_sync(0xffffffffu, p[i], j);
                O[i][0] += pj * v0; O[i][1] += pj * v1;
                O[i][2] += pj * v2; O[i][3] += pj * v3;
            }
        }
    }

#pragma unroll
    for (int i = 0; i < 4; i++) {
        int r = q0 + row0 + i;
        if (r < L) {
            int e = g_list[m*E_ + r];
            int t = e >> 2, a = e & 3;
            float wgt = g_kvw[t*A_ + a] / lr[i];
#pragma unroll
            for (int c = 0; c < 4; c++)
                g_ao[t*(A_*QH_*D_) + ((a*QH_ + h) << 7) + lane + 32*c] = O[i][c] * wgt;
        }
    }
}

// ---------------- launch ----------------
extern "C" void kernel_launch(void* const* d_in, const int* in_sizes, int n_in,
                              void* d_out, int out_size)
{
    const float* x  = (const float*)d_in[0];
    const float* wq = (const float*)d_in[1];
    const float* wk = (const float*)d_in[2];
    const float* wv = (const float*)d_in[3];
    const float* wr = (const float*)d_in[4];
    const float* wo = (const float*)d_in[5];
    float* out = (float*)d_out;

    float *yq, *yk, *yv, *ao;
    cudaGetSymbolAddress((void**)&yq, g_yq);
    cudaGetSymbolAddress((void**)&yk, g_yk);
    cudaGetSymbolAddress((void**)&yv, g_yv);
    cudaGetSymbolAddress((void**)&ao, g_ao);

    router_kernel<<<S_/4, 128>>>(x, wr);
    build_lists_kernel<<<1, 128>>>();
    aux_reduce_kernel<<<1, 256>>>(out, out_size);

    sgemm_tn<<<dim3(12, 8), 256>>>(x, wq, yq, S_, M_*QH_*D_, EMB_);
    sgemm_tn<<<dim3( 6, 8), 256>>>(x, wk, yk, S_, M_*D_,     EMB_);
    sgemm_tn<<<dim3( 6, 8), 256>>>(x, wv, yv, S_, M_*D_,     EMB_);

    gather_rope_kernel<<<E_, 128>>>();
    attn_kernel<<<dim3(E_/TQ, QH_, M_), 256>>>();

    sgemm_tn<<<dim3(8, 8), 256>>>(ao, wo, out, S_, EMB_, EMB_);
}

// round 2
// speedup vs baseline: 1.8686x; 1.8686x over previous
#include <cuda_runtime.h>
#include <cuda_bf16.h>
#include <math.h>
#include <stdint.h>

#define S_    1024
#define EMB_  1024
#define M_    6
#define A_    4
#define QH_   2
#define D_    128
#define E_    (S_*A_)

// ---------------- scratch (static device globals; no allocation) ----------------
__device__ float g_yq[S_*M_*QH_*D_];     // 1024 x 1536
__device__ float g_yk[S_*M_*D_];         // 1024 x 768
__device__ float g_yv[S_*M_*D_];         // 1024 x 768
__device__ float g_probs[S_*M_];
__device__ float g_ent[S_];
__device__ int   g_primary[S_];
__device__ int   g_kvidx[E_];
__device__ float g_kvw[E_];
__device__ int   g_rank[E_];
__device__ int   g_list[M_*E_];
__device__ int   g_counts[M_];
__device__ float g_qsrt[M_*E_*QH_*D_];
__device__ float g_ksrt[M_*E_*D_];
__device__ float g_vsrt[M_*E_*D_];
__device__ float g_ao[S_*A_*QH_*D_];     // 1024 x 1024 pre-output

// ---------------- router ----------------
__global__ void router_kernel(const float* __restrict__ x, const float* __restrict__ wr) {
    int gw   = (blockIdx.x * blockDim.x + threadIdx.x) >> 5;
    int lane = threadIdx.x & 31;
    if (gw >= S_) return;
    const float* xr = x + gw * EMB_;
    float acc[M_];
#pragma unroll
    for (int m = 0; m < M_; m++) acc[m] = 0.f;
    for (int i = lane; i < EMB_; i += 32) {
        float xv = xr[i];
#pragma unroll
        for (int m = 0; m < M_; m++) acc[m] += xv * wr[m*EMB_ + i];
    }
#pragma unroll
    for (int m = 0; m < M_; m++)
        for (int o = 16; o; o >>= 1) acc[m] += __shfl_xor_sync(0xffffffffu, acc[m], o);
    if (lane == 0) {
        float mx = acc[0];
#pragma unroll
        for (int m = 1; m < M_; m++) mx = fmaxf(mx, acc[m]);
        float ex[M_], ssum = 0.f;
#pragma unroll
        for (int m = 0; m < M_; m++) { ex[m] = expf(acc[m] - mx); ssum += ex[m]; }
        float inv = 1.f / ssum;
        float ent = 0.f;
#pragma unroll
        for (int m = 0; m < M_; m++) {
            float p = ex[m] * inv;
            g_probs[gw*M_ + m] = p;
            ent -= p * logf(p + 1e-8f);
        }
        g_ent[gw] = ent;
        float v[M_];
#pragma unroll
        for (int m = 0; m < M_; m++) v[m] = acc[m];
        int   idx[A_]; float tv[A_];
#pragma unroll
        for (int a = 0; a < A_; a++) {
            float best = -INFINITY; int bi = 0;
#pragma unroll
            for (int m = 0; m < M_; m++) if (v[m] > best) { best = v[m]; bi = m; }
            idx[a] = bi; tv[a] = best; v[bi] = -INFINITY;
        }
        float wv[A_], ws = 0.f;
#pragma unroll
        for (int a = 0; a < A_; a++) { wv[a] = expf(tv[a] - tv[0]); ws += wv[a]; }
        float winv = 1.f / ws;
#pragma unroll
        for (int a = 0; a < A_; a++) {
            g_kvidx[gw*A_ + a] = idx[a];
            g_kvw  [gw*A_ + a] = wv[a] * winv;
        }
        g_primary[gw] = idx[0];
    }
}

// ---------------- per-expert lists + ranks ----------------
__global__ void build_lists_kernel() {
    __shared__ int sg[E_];
    for (int i = threadIdx.x; i < E_; i += blockDim.x) sg[i] = g_kvidx[i];
    __syncthreads();
    int m = threadIdx.x;
    if (m < M_) {
        int c = 0;
        for (int e = 0; e < E_; e++) {
            if (sg[e] == m) { g_rank[e] = c; g_list[m*E_ + c] = e; c++; }
        }
        g_counts[m] = c;
    }
}

// ---------------- aux loss ----------------
__global__ void aux_reduce_kernel(float* __restrict__ d_out, int out_size) {
    __shared__ float red[256];
    __shared__ float tot[13];
    int tid = threadIdx.x;
    float pf[M_], pp[M_], pe = 0.f;
#pragma unroll
    for (int m = 0; m < M_; m++) { pf[m] = 0.f; pp[m] = 0.f; }
    for (int t = tid; t < S_; t += 256) {
        int pm = g_primary[t];
        pe += g_ent[t];
#pragma unroll
        for (int m = 0; m < M_; m++) {
            pp[m] += g_probs[t*M_ + m];
            pf[m] += (pm == m) ? 1.f : 0.f;
        }
    }
    for (int q = 0; q < 13; q++) {
        float v = (q < 6) ? pf[q] : (q < 12 ? pp[q-6] : pe);
        red[tid] = v; __syncthreads();
        for (int s = 128; s > 0; s >>= 1) {
            if (tid < s) red[tid] += red[tid + s];
            __syncthreads();
        }
        if (tid == 0) tot[q] = red[0];
        __syncthreads();
    }
    if (tid == 0) {
        float bal = 0.f;
#pragma unroll
        for (int m = 0; m < M_; m++) bal += (tot[m] / (float)S_) * (tot[6+m] / (float)S_);
        bal *= (float)M_;
        float aux = 0.01f * bal - 0.01f * (tot[12] / (float)S_);
        d_out[out_size - 1] = aux;
    }
}

// ---------------- tensor-core GEMM: bf16 3-pass split (hi*hi + hi*lo + lo*hi) ----------------
__device__ __forceinline__ uint32_t smem_u32(const void* p) {
    return (uint32_t)__cvta_generic_to_shared(p);
}
__device__ __forceinline__ void ldsm4(uint32_t* r, const void* p) {
    uint32_t a = smem_u32(p);
    asm volatile("ldmatrix.sync.aligned.m8n8.x4.shared.b16 {%0,%1,%2,%3}, [%4];"
                 : "=r"(r[0]), "=r"(r[1]), "=r"(r[2]), "=r"(r[3]) : "r"(a));
}
__device__ __forceinline__ void mma16816(float* c, const uint32_t* a, uint32_t b0, uint32_t b1) {
    asm volatile("mma.sync.aligned.m16n8k16.row.col.f32.bf16.bf16.f32 "
                 "{%0,%1,%2,%3}, {%4,%5,%6,%7}, {%8,%9}, {%0,%1,%2,%3};"
                 : "+f"(c[0]), "+f"(c[1]), "+f"(c[2]), "+f"(c[3])
                 : "r"(a[0]), "r"(a[1]), "r"(a[2]), "r"(a[3]), "r"(b0), "r"(b1));
}
__device__ __forceinline__ void cvt4(float4 v, uint2& hi, uint2& lo) {
    __nv_bfloat16 h0 = __float2bfloat16(v.x), h1 = __float2bfloat16(v.y);
    __nv_bfloat16 h2 = __float2bfloat16(v.z), h3 = __float2bfloat16(v.w);
    __nv_bfloat16 l0 = __float2bfloat16(v.x - __bfloat162float(h0));
    __nv_bfloat16 l1 = __float2bfloat16(v.y - __bfloat162float(h1));
    __nv_bfloat16 l2 = __float2bfloat16(v.z - __bfloat162float(h2));
    __nv_bfloat16 l3 = __float2bfloat16(v.w - __bfloat162float(h3));
    __nv_bfloat162 H0, H1, L0, L1;
    H0.x = h0; H0.y = h1; H1.x = h2; H1.y = h3;
    L0.x = l0; L0.y = l1; L1.x = l2; L1.y = l3;
    hi.x = *(uint32_t*)&H0; hi.y = *(uint32_t*)&H1;
    lo.x = *(uint32_t*)&L0; lo.y = *(uint32_t*)&L1;
}

// C_s[128-row-block y][128-col-block x] = A * B_s^T; up to 3 output segments.
__global__ __launch_bounds__(256) void gemm3seg(
    const float* __restrict__ A,
    const float* __restrict__ B0, const float* __restrict__ B1, const float* __restrict__ B2,
    float* __restrict__ C0, float* __restrict__ C1, float* __restrict__ C2,
    int K, int nb0, int nb1, int N0, int N1, int N2)
{
    __shared__ __nv_bfloat16 Ahi[128][40], Alo[128][40], Bhi[128][40], Blo[128][40];
    int tid = threadIdx.x, lane = tid & 31, warp = tid >> 5;
    int wm = warp >> 1, wn = warp & 1;

    const float* Bp; float* Cp; int N; int bxl = blockIdx.x;
    if (bxl < nb0)             { Bp = B0; Cp = C0; N = N0; }
    else if (bxl < nb0 + nb1)  { Bp = B1; Cp = C1; N = N1; bxl -= nb0; }
    else                       { Bp = B2; Cp = C2; N = N2; bxl -= nb0 + nb1; }

    int arow = tid >> 1;
    int kq   = (tid & 1) * 16;
    const float* Ag = A  + (size_t)(blockIdx.y * 128 + arow) * K + kq;
    const float* Bg = Bp + (size_t)(bxl       * 128 + arow) * K + kq;

    float acc[2][8][4];
#pragma unroll
    for (int mt = 0; mt < 2; mt++)
#pragma unroll
        for (int nt = 0; nt < 8; nt++)
#pragma unroll
            for (int c = 0; c < 4; c++) acc[mt][nt][c] = 0.f;

    int g   = lane >> 3;
    int lr  = (lane & 7) + ((g & 1) << 3);   // A: row offset in 16-row tile
    int lcA = (g >> 1) << 3;                 // A: k offset (0 or 8)
    int brn = (lane & 7) + ((g >> 1) << 3);  // B: n offset in 16-col group
    int lcB = (g & 1) << 3;                  // B: k offset (0 or 8)

    float4 Ar[4], Br[4];
#pragma unroll
    for (int j = 0; j < 4; j++) {
        Ar[j] = *(const float4*)(Ag + 4*j);
        Br[j] = *(const float4*)(Bg + 4*j);
    }

    for (int kt = 0; kt < K; kt += 32) {
        __syncthreads();
#pragma unroll
        for (int j = 0; j < 4; j++) {
            int kk = kq + 4*j;
            uint2 h, l;
            cvt4(Ar[j], h, l);
            *(uint2*)&Ahi[arow][kk] = h;
            *(uint2*)&Alo[arow][kk] = l;
            cvt4(Br[j], h, l);
            *(uint2*)&Bhi[arow][kk] = h;
            *(uint2*)&Blo[arow][kk] = l;
        }
        __syncthreads();
        int ktn = (kt + 32 < K) ? kt + 32 : 0;   // harmless reload on last iter
#pragma unroll
        for (int j = 0; j < 4; j++) {
            Ar[j] = *(const float4*)(Ag + ktn + 4*j);
            Br[j] = *(const float4*)(Bg + ktn + 4*j);
        }
#pragma unroll
        for (int kh = 0; kh < 2; kh++) {
            uint32_t ah[2][4], al[2][4], bh[4][4], bl[4][4];
#pragma unroll
            for (int mt = 0; mt < 2; mt++) {
                int r = wm*32 + mt*16 + lr;
                int c = kh*16 + lcA;
                ldsm4(ah[mt], &Ahi[r][c]);
                ldsm4(al[mt], &Alo[r][c]);
            }
#pragma unroll
            for (int j = 0; j < 4; j++) {
                int r = wn*64 + j*16 + brn;
                int c = kh*16 + lcB;
                ldsm4(bh[j], &Bhi[r][c]);
                ldsm4(bl[j], &Blo[r][c]);
            }
#pragma unroll
            for (int mt = 0; mt < 2; mt++)
#pragma unroll
                for (int nt = 0; nt < 8; nt++) {
                    uint32_t b0h = bh[nt>>1][(nt&1)*2], b1h = bh[nt>>1][(nt&1)*2+1];
                    uint32_t b0l = bl[nt>>1][(nt&1)*2], b1l = bl[nt>>1][(nt&1)*2+1];
                    mma16816(acc[mt][nt], ah[mt], b0h, b1h);
                    mma16816(acc[mt][nt], ah[mt], b0l, b1l);
                    mma16816(acc[mt][nt], al[mt], b0h, b1h);
                }
        }
    }

    int crow0 = blockIdx.y*128 + wm*32 + (lane >> 2);
    int ccol0 = bxl*128 + wn*64 + (lane & 3)*2;
#pragma unroll
    for (int mt = 0; mt < 2; mt++)
#pragma unroll
        for (int nt = 0; nt < 8; nt++) {
            float* p = Cp + (size_t)(crow0 + mt*16) * N + ccol0 + nt*8;
            *(float2*)p           = make_float2(acc[mt][nt][0], acc[mt][nt][1]);
            *(float2*)(p + 8*N)   = make_float2(acc[mt][nt][2], acc[mt][nt][3]);
        }
}

// ---------------- gather + RoPE (pos = rank) ----------------
__global__ void gather_rope_kernel() {
    int e = blockIdx.x;
    int d = threadIdx.x;
    int m = g_kvidx[e];
    int r = g_rank[e];
    int t = e >> 2;
    int dm = d & 63;
    float invf = expf(-(float)dm * (9.210340371976184f / 64.0f));
    float fr = (float)r * invf;
    float sn, cs;
    sincosf(fr, &sn, &cs);
    int   partner = (d < 64) ? d + 64 : d - 64;
    float sgn     = (d < 64) ? -1.f : 1.f;
    int ro = m * E_ + r;
    const float* kb = g_yk + t * (M_ * D_) + m * D_;
    g_ksrt[ro*D_ + d] = kb[d] * cs + sgn * kb[partner] * sn;
    g_vsrt[ro*D_ + d] = g_yv[t*(M_*D_) + m*D_ + d];
#pragma unroll
    for (int h = 0; h < QH_; h++) {
        const float* qb = g_yq + t * (M_*QH_*D_) + (m*QH_ + h) * D_;
        g_qsrt[(ro*QH_ + h)*D_ + d] = qb[d] * cs + sgn * qb[partner] * sn;
    }
}

// ---------------- flash attention per (expert, head, q-tile) ----------------
#define TQ 32
#define TK 32
__global__ __launch_bounds__(256) void attn_kernel() {
    int m = blockIdx.z, h = blockIdx.y;
    int L = g_counts[m];
    int q0 = blockIdx.x * TQ;
    if (q0 >= L) return;

    __shared__ float Qs[TQ * 128];
    __shared__ float KV[128 * 33];

    int tid = threadIdx.x, w = tid >> 5, lane = tid & 31;
    int row0 = w * 4;

    for (int idx = tid; idx < TQ*128; idx += 256) {
        int i = idx >> 7, d = idx & 127;
        int r = q0 + i;
        Qs[idx] = (r < L) ? g_qsrt[((m*E_ + r)*QH_ + h)*D_ + d] : 0.f;
    }

    float O[4][4];
#pragma unroll
    for (int i = 0; i < 4; i++)
#pragma unroll
        for (int c = 0; c < 4; c++) O[i][c] = 0.f;
    float mr[4] = {-INFINITY, -INFINITY, -INFINITY, -INFINITY};
    float lr[4] = {0.f, 0.f, 0.f, 0.f};
    const float scale = 0.08838834764831845f;

    for (int kt = 0; kt < L; kt += TK) {
        __syncthreads();
        for (int idx = tid; idx < TK*128; idx += 256) {
            int j = idx >> 7, d = idx & 127;
            int kk = kt + j;
            KV[d*33 + j] = (kk < L) ? g_ksrt[(m*E_ + kk)*D_ + d] : 0.f;
        }
        __syncthreads();

        float s[4] = {0.f, 0.f, 0.f, 0.f};
#pragma unroll 4
        for (int d = 0; d < 128; d++) {
            float kv = KV[d*33 + lane];
            s[0] += Qs[(row0+0)*128 + d] * kv;
            s[1] += Qs[(row0+1)*128 + d] * kv;
            s[2] += Qs[(row0+2)*128 + d] * kv;
            s[3] += Qs[(row0+3)*128 + d] * kv;
        }
        bool kvalid = (kt + lane) < L;
        float p[4];
#pragma unroll
        for (int i = 0; i < 4; i++) {
            float sv = kvalid ? s[i] * scale : -1e30f;
            float smax = sv;
            for (int o = 16; o; o >>= 1) smax = fmaxf(smax, __shfl_xor_sync(0xffffffffu, smax, o));
            float nm = fmaxf(mr[i], smax);
            p[i] = expf(sv - nm);
            float corr = expf(mr[i] - nm);
            float ps = p[i];
            for (int o = 16; o; o >>= 1) ps += __shfl_xor_sync(0xffffffffu, ps, o);
            lr[i] = lr[i] * corr + ps;
#pragma unroll
            for (int c = 0; c < 4; c++) O[i][c] *= corr;
            mr[i] = nm;
        }

        __syncthreads();
        for (int idx = tid; idx < TK*128; idx += 256) {
            int j = idx >> 7, d = idx & 127;
            int kk = kt + j;
            KV[j*128 + d] = (kk < L) ? g_vsrt[(m*E_ + kk)*D_ + d] : 0.f;
        }
        __syncthreads();

#pragma unroll 4
        for (int j = 0; j < 32; j++) {
            float v0 = KV[j*128 + lane];
            float v1 = KV[j*128 + lane + 32];
            float v2 = KV[j*128 + lane + 64];
            float v3 = KV[j*128 + lane + 96];
#pragma unroll
            for (int i = 0; i < 4; i++) {
                float pj = __shfl_sync(0xffffffffu, p[i], j);
                O[i][0] += pj * v0; O[i][1] += pj * v1;
                O[i][2] += pj * v2; O[i][3] += pj * v3;
            }
        }
    }

#pragma unroll
    for (int i = 0; i < 4; i++) {
        int r = q0 + row0 + i;
        if (r < L) {
            int e = g_list[m*E_ + r];
            int t = e >> 2, a = e & 3;
            float wgt = g_kvw[t*A_ + a] / lr[i];
#pragma unroll
            for (int c = 0; c < 4; c++)
                g_ao[t*(A_*QH_*D_) + ((a*QH_ + h) << 7) + lane + 32*c] = O[i][c] * wgt;
        }
    }
}

// ---------------- launch ----------------
extern "C" void kernel_launch(void* const* d_in, const int* in_sizes, int n_in,
                              void* d_out, int out_size)
{
    const float* x  = (const float*)d_in[0];
    const float* wq = (const float*)d_in[1];
    const float* wk = (const float*)d_in[2];
    const float* wv = (const float*)d_in[3];
    const float* wr = (const float*)d_in[4];
    const float* wo = (const float*)d_in[5];
    float* out = (float*)d_out;

    float *yq, *yk, *yv, *ao;
    cudaGetSymbolAddress((void**)&yq, g_yq);
    cudaGetSymbolAddress((void**)&yk, g_yk);
    cudaGetSymbolAddress((void**)&yv, g_yv);
    cudaGetSymbolAddress((void**)&ao, g_ao);

    router_kernel<<<S_/4, 128>>>(x, wr);
    build_lists_kernel<<<1, 128>>>();
    aux_reduce_kernel<<<1, 256>>>(out, out_size);

    // fused Q/K/V projections: 12 + 6 + 6 = 24 column blocks x 8 row blocks
    gemm3seg<<<dim3(24, 8), 256>>>(x, wq, wk, wv, yq, yk, yv,
                                   EMB_, 12, 6, M_*QH_*D_, M_*D_, M_*D_);

    gather_rope_kernel<<<E_, 128>>>();
    attn_kernel<<<dim3(E_/TQ, QH_, M_), 256>>>();

    // output projection
    gemm3seg<<<dim3(8, 8), 256>>>(ao, wo, nullptr, nullptr, out, nullptr, nullptr,
                                  EMB_, 8, 0, EMB_, 0, 0);
}

// round 3
// speedup vs baseline: 3.7965x; 2.0317x over previous
#include <cuda_runtime.h>
#include <cuda_bf16.h>
#include <math.h>
#include <stdint.h>

#define S_    1024
#define EMB_  1024
#define M_    6
#define A_    4
#define QH_   2
#define D_    128
#define E_    (S_*A_)

// ---------------- scratch (static device globals; no allocation) ----------------
__device__ float g_yq[S_*M_*QH_*D_];
__device__ float g_yk[S_*M_*D_];
__device__ float g_yv[S_*M_*D_];
__device__ float g_probs[S_*M_];
__device__ float g_ent[S_];
__device__ int   g_primary[S_];
__device__ int   g_kvidx[E_];
__device__ float g_kvw[E_];
__device__ int   g_rank[E_];
__device__ int   g_list[M_*E_];
__device__ int   g_counts[M_];
__device__ float g_qsrt[M_*E_*QH_*D_];   // per-expert RoPE'd Q (scaled), dense by rank
__device__ float g_ksrt[M_*E_*D_];
__device__ float g_vsrtT[M_*D_*E_];      // V transposed: [m][d][rank]
__device__ float g_ao[S_*A_*QH_*D_];
__device__ float g_part[2*S_*EMB_];      // split-K partials for out projection

// ---------------- router ----------------
__global__ void router_kernel(const float* __restrict__ x, const float* __restrict__ wr) {
    int gw   = (blockIdx.x * blockDim.x + threadIdx.x) >> 5;
    int lane = threadIdx.x & 31;
    if (gw >= S_) return;
    const float* xr = x + gw * EMB_;
    float acc[M_];
#pragma unroll
    for (int m = 0; m < M_; m++) acc[m] = 0.f;
    for (int i = lane; i < EMB_; i += 32) {
        float xv = xr[i];
#pragma unroll
        for (int m = 0; m < M_; m++) acc[m] += xv * wr[m*EMB_ + i];
    }
#pragma unroll
    for (int m = 0; m < M_; m++)
        for (int o = 16; o; o >>= 1) acc[m] += __shfl_xor_sync(0xffffffffu, acc[m], o);
    if (lane == 0) {
        float mx = acc[0];
#pragma unroll
        for (int m = 1; m < M_; m++) mx = fmaxf(mx, acc[m]);
        float ex[M_], ssum = 0.f;
#pragma unroll
        for (int m = 0; m < M_; m++) { ex[m] = expf(acc[m] - mx); ssum += ex[m]; }
        float inv = 1.f / ssum;
        float ent = 0.f;
#pragma unroll
        for (int m = 0; m < M_; m++) {
            float p = ex[m] * inv;
            g_probs[gw*M_ + m] = p;
            ent -= p * logf(p + 1e-8f);
        }
        g_ent[gw] = ent;
        float v[M_];
#pragma unroll
        for (int m = 0; m < M_; m++) v[m] = acc[m];
        int   idx[A_]; float tv[A_];
#pragma unroll
        for (int a = 0; a < A_; a++) {
            float best = -INFINITY; int bi = 0;
#pragma unroll
            for (int m = 0; m < M_; m++) if (v[m] > best) { best = v[m]; bi = m; }
            idx[a] = bi; tv[a] = best; v[bi] = -INFINITY;
        }
        float wv[A_], ws = 0.f;
#pragma unroll
        for (int a = 0; a < A_; a++) { wv[a] = expf(tv[a] - tv[0]); ws += wv[a]; }
        float winv = 1.f / ws;
#pragma unroll
        for (int a = 0; a < A_; a++) {
            g_kvidx[gw*A_ + a] = idx[a];
            g_kvw  [gw*A_ + a] = wv[a] * winv;
        }
        g_primary[gw] = idx[0];
    }
}

// ---------------- per-expert lists + ranks: one warp per expert, ballot scan ----------------
__global__ void build_lists_kernel() {
    int m    = threadIdx.x >> 5;
    int lane = threadIdx.x & 31;
    if (m >= M_) return;
    int base = 0;
    for (int e0 = 0; e0 < E_; e0 += 32) {
        int e = e0 + lane;
        int gidx = g_kvidx[e];
        unsigned mask = __ballot_sync(0xffffffffu, gidx == m);
        if (gidx == m) {
            int r = base + __popc(mask & ((1u << lane) - 1u));
            g_rank[e] = r;
            g_list[m*E_ + r] = e;
        }
        base += __popc(mask);
    }
    if (lane == 0) g_counts[m] = base;
}

// ---------------- aux loss ----------------
__global__ void aux_reduce_kernel(float* __restrict__ d_out, int out_size) {
    __shared__ float red[256];
    __shared__ float tot[13];
    int tid = threadIdx.x;
    float pf[M_], pp[M_], pe = 0.f;
#pragma unroll
    for (int m = 0; m < M_; m++) { pf[m] = 0.f; pp[m] = 0.f; }
    for (int t = tid; t < S_; t += 256) {
        int pm = g_primary[t];
        pe += g_ent[t];
#pragma unroll
        for (int m = 0; m < M_; m++) {
            pp[m] += g_probs[t*M_ + m];
            pf[m] += (pm == m) ? 1.f : 0.f;
        }
    }
    for (int q = 0; q < 13; q++) {
        float v = (q < 6) ? pf[q] : (q < 12 ? pp[q-6] : pe);
        red[tid] = v; __syncthreads();
        for (int s = 128; s > 0; s >>= 1) {
            if (tid < s) red[tid] += red[tid + s];
            __syncthreads();
        }
        if (tid == 0) tot[q] = red[0];
        __syncthreads();
    }
    if (tid == 0) {
        float bal = 0.f;
#pragma unroll
        for (int m = 0; m < M_; m++) bal += (tot[m] / (float)S_) * (tot[6+m] / (float)S_);
        bal *= (float)M_;
        float aux = 0.01f * bal - 0.01f * (tot[12] / (float)S_);
        d_out[out_size - 1] = aux;
    }
}

// ---------------- mma helpers ----------------
__device__ __forceinline__ uint32_t smem_u32(const void* p) {
    return (uint32_t)__cvta_generic_to_shared(p);
}
__device__ __forceinline__ void ldsm4(uint32_t* r, const void* p) {
    uint32_t a = smem_u32(p);
    asm volatile("ldmatrix.sync.aligned.m8n8.x4.shared.b16 {%0,%1,%2,%3}, [%4];"
                 : "=r"(r[0]), "=r"(r[1]), "=r"(r[2]), "=r"(r[3]) : "r"(a));
}
__device__ __forceinline__ void mma16816(float* c, const uint32_t* a, uint32_t b0, uint32_t b1) {
    asm volatile("mma.sync.aligned.m16n8k16.row.col.f32.bf16.bf16.f32 "
                 "{%0,%1,%2,%3}, {%4,%5,%6,%7}, {%8,%9}, {%0,%1,%2,%3};"
                 : "+f"(c[0]), "+f"(c[1]), "+f"(c[2]), "+f"(c[3])
                 : "r"(a[0]), "r"(a[1]), "r"(a[2]), "r"(a[3]), "r"(b0), "r"(b1));
}
__device__ __forceinline__ void cvt4(float4 v, uint2& hi, uint2& lo) {
    __nv_bfloat16 h0 = __float2bfloat16(v.x), h1 = __float2bfloat16(v.y);
    __nv_bfloat16 h2 = __float2bfloat16(v.z), h3 = __float2bfloat16(v.w);
    __nv_bfloat16 l0 = __float2bfloat16(v.x - __bfloat162float(h0));
    __nv_bfloat16 l1 = __float2bfloat16(v.y - __bfloat162float(h1));
    __nv_bfloat16 l2 = __float2bfloat16(v.z - __bfloat162float(h2));
    __nv_bfloat16 l3 = __float2bfloat16(v.w - __bfloat162float(h3));
    __nv_bfloat162 H0, H1, L0, L1;
    H0.x = h0; H0.y = h1; H1.x = h2; H1.y = h3;
    L0.x = l0; L0.y = l1; L1.x = l2; L1.y = l3;
    hi.x = *(uint32_t*)&H0; hi.y = *(uint32_t*)&H1;
    lo.x = *(uint32_t*)&L0; lo.y = *(uint32_t*)&L1;
}
__device__ __forceinline__ void packhl(float x, float y, uint32_t& hi, uint32_t& lo) {
    __nv_bfloat162 H, L;
    H.x = __float2bfloat16(x); H.y = __float2bfloat16(y);
    L.x = __float2bfloat16(x - __bfloat162float(H.x));
    L.y = __float2bfloat16(y - __bfloat162float(H.y));
    hi = *(uint32_t*)&H; lo = *(uint32_t*)&L;
}

// ---------------- GEMM: double-buffered, 3-seg, optional split-K over blockIdx.z ----------------
// C[128y][128x] = A[128x K] * B[128x K]^T ; bf16 3-pass (hi*hi + hi*lo + lo*hi)
__global__ __launch_bounds__(256) void gemm3seg(
    const float* __restrict__ A,
    const float* __restrict__ B0, const float* __restrict__ B1, const float* __restrict__ B2,
    float* __restrict__ C0, float* __restrict__ C1, float* __restrict__ C2,
    int K, int nb0, int nb1, int N0, int N1, int N2)
{
    extern __shared__ __nv_bfloat16 ds[];
    // per stage: Ahi,Alo,Bhi,Blo each 128x40
    const int ST = 4*128*40; // 20480 bf16 per stage
    int tid = threadIdx.x, lane = tid & 31, warp = tid >> 5;
    int wm = warp >> 1, wn = warp & 1;

    int Klen = K / gridDim.z;
    int kOff = blockIdx.z * Klen;

    const float* Bp; float* Cp; int N; int bxl = blockIdx.x;
    if (bxl < nb0)             { Bp = B0; Cp = C0; N = N0; }
    else if (bxl < nb0 + nb1)  { Bp = B1; Cp = C1; N = N1; bxl -= nb0; }
    else                       { Bp = B2; Cp = C2; N = N2; bxl -= nb0 + nb1; }
    Cp += (size_t)blockIdx.z * S_ * N;

    int arow = tid >> 1;
    int kq   = (tid & 1) * 16;
    const float* Ag = A  + (size_t)(blockIdx.y * 128 + arow) * K + kOff + kq;
    const float* Bg = Bp + (size_t)(bxl       * 128 + arow) * K + kOff + kq;

    float acc[2][8][4];
#pragma unroll
    for (int mt = 0; mt < 2; mt++)
#pragma unroll
        for (int nt = 0; nt < 8; nt++)
#pragma unroll
            for (int c = 0; c < 4; c++) acc[mt][nt][c] = 0.f;

    int g   = lane >> 3;
    int lr  = (lane & 7) + ((g & 1) << 3);
    int lcA = (g >> 1) << 3;
    int brn = (lane & 7) + ((g >> 1) << 3);
    int lcB = (g & 1) << 3;

    float4 Ar[4], Br[4];
#pragma unroll
    for (int j = 0; j < 4; j++) {
        Ar[j] = *(const float4*)(Ag + 4*j);
        Br[j] = *(const float4*)(Bg + 4*j);
    }
    // store stage 0
    {
        __nv_bfloat16* Ahi = ds; __nv_bfloat16* Alo = ds + 128*40;
        __nv_bfloat16* Bhi = ds + 2*128*40; __nv_bfloat16* Blo = ds + 3*128*40;
#pragma unroll
        for (int j = 0; j < 4; j++) {
            int kk = kq + 4*j;
            uint2 h, l;
            cvt4(Ar[j], h, l);
            *(uint2*)&Ahi[arow*40 + kk] = h;
            *(uint2*)&Alo[arow*40 + kk] = l;
            cvt4(Br[j], h, l);
            *(uint2*)&Bhi[arow*40 + kk] = h;
            *(uint2*)&Blo[arow*40 + kk] = l;
        }
    }
    __syncthreads();

    for (int kt = 0; kt < Klen; kt += 32) {
        int cur = (kt >> 5) & 1;
        bool more = (kt + 32) < Klen;
        if (more) {
#pragma unroll
            for (int j = 0; j < 4; j++) {
                Ar[j] = *(const float4*)(Ag + kt + 32 + 4*j);
                Br[j] = *(const float4*)(Bg + kt + 32 + 4*j);
            }
        }
        const __nv_bfloat16* Ahi = ds + cur*ST;
        const __nv_bfloat16* Alo = Ahi + 128*40;
        const __nv_bfloat16* Bhi = Ahi + 2*128*40;
        const __nv_bfloat16* Blo = Ahi + 3*128*40;
#pragma unroll
        for (int kh = 0; kh < 2; kh++) {
            uint32_t ah[2][4], al[2][4], bh[4][4], bl[4][4];
#pragma unroll
            for (int mt = 0; mt < 2; mt++) {
                int r = wm*32 + mt*16 + lr;
                int c = kh*16 + lcA;
                ldsm4(ah[mt], &Ahi[r*40 + c]);
                ldsm4(al[mt], &Alo[r*40 + c]);
            }
#pragma unroll
            for (int j = 0; j < 4; j++) {
                int r = wn*64 + j*16 + brn;
                int c = kh*16 + lcB;
                ldsm4(bh[j], &Bhi[r*40 + c]);
                ldsm4(bl[j], &Blo[r*40 + c]);
            }
#pragma unroll
            for (int mt = 0; mt < 2; mt++)
#pragma unroll
                for (int nt = 0; nt < 8; nt++) {
                    uint32_t b0h = bh[nt>>1][(nt&1)*2], b1h = bh[nt>>1][(nt&1)*2+1];
                    uint32_t b0l = bl[nt>>1][(nt&1)*2], b1l = bl[nt>>1][(nt&1)*2+1];
                    mma16816(acc[mt][nt], ah[mt], b0h, b1h);
                    mma16816(acc[mt][nt], ah[mt], b0l, b1l);
                    mma16816(acc[mt][nt], al[mt], b0h, b1h);
                }
        }
        if (more) {
            __nv_bfloat16* Ahi2 = ds + (cur^1)*ST;
            __nv_bfloat16* Alo2 = Ahi2 + 128*40;
            __nv_bfloat16* Bhi2 = Ahi2 + 2*128*40;
            __nv_bfloat16* Blo2 = Ahi2 + 3*128*40;
#pragma unroll
            for (int j = 0; j < 4; j++) {
                int kk = kq + 4*j;
                uint2 h, l;
                cvt4(Ar[j], h, l);
                *(uint2*)&Ahi2[arow*40 + kk] = h;
                *(uint2*)&Alo2[arow*40 + kk] = l;
                cvt4(Br[j], h, l);
                *(uint2*)&Bhi2[arow*40 + kk] = h;
                *(uint2*)&Blo2[arow*40 + kk] = l;
            }
        }
        __syncthreads();
    }

    int crow0 = blockIdx.y*128 + wm*32 + (lane >> 2);
    int ccol0 = bxl*128 + wn*64 + (lane & 3)*2;
#pragma unroll
    for (int mt = 0; mt < 2; mt++)
#pragma unroll
        for (int nt = 0; nt < 8; nt++) {
            float* p = Cp + (size_t)(crow0 + mt*16) * N + ccol0 + nt*8;
            *(float2*)p           = make_float2(acc[mt][nt][0], acc[mt][nt][1]);
            *(float2*)(p + 8*N)   = make_float2(acc[mt][nt][2], acc[mt][nt][3]);
        }
}

// ---------------- sum split-K partials into d_out ----------------
__global__ void add_out_kernel(float* __restrict__ out) {
    int i = blockIdx.x * 256 + threadIdx.x;
    out[i] = g_part[i] + g_part[i + S_*EMB_];
}

// ---------------- gather + RoPE (pos = rank); Q pre-scaled; V transposed ----------------
__global__ void gather_rope_kernel() {
    int e = blockIdx.x;
    int d = threadIdx.x;
    int m = g_kvidx[e];
    int r = g_rank[e];
    int t = e >> 2;
    int dm = d & 63;
    float invf = expf(-(float)dm * (9.210340371976184f / 64.0f));
    float fr = (float)r * invf;
    float sn, cs;
    sincosf(fr, &sn, &cs);
    int   partner = (d < 64) ? d + 64 : d - 64;
    float sgn     = (d < 64) ? -1.f : 1.f;
    int ro = m * E_ + r;
    const float scale = 0.08838834764831845f; // 1/sqrt(128), folded into Q
    const float* kb = g_yk + t * (M_ * D_) + m * D_;
    g_ksrt[ro*D_ + d] = kb[d] * cs + sgn * kb[partner] * sn;
    g_vsrtT[(m*D_ + d)*E_ + r] = g_yv[t*(M_*D_) + m*D_ + d];
#pragma unroll
    for (int h = 0; h < QH_; h++) {
        const float* qb = g_yq + t * (M_*QH_*D_) + (m*QH_ + h) * D_;
        g_qsrt[(ro*QH_ + h)*D_ + d] = (qb[d] * cs + sgn * qb[partner] * sn) * scale;
    }
}

// ---------------- tensor-core flash attention: 64 q-rows x 64 k-cols, 4 warps ----------------
// smem (bf16 elems): Qh 64x136 | Ql | Kh 64x136 | Kl | Vh 128x72 | Vl
#define AQH0 0
#define AQL0 8704
#define AKH0 17408
#define AKL0 26112
#define AVH0 34816
#define AVL0 44032
#define ATTN_SMEM_BYTES (53248*2)

__global__ __launch_bounds__(128) void attn_kernel() {
    int m = blockIdx.z, h = blockIdx.y;
    int L = g_counts[m];
    int q0 = blockIdx.x * 64;
    if (q0 >= L) return;

    extern __shared__ __nv_bfloat16 as[];
    int tid = threadIdx.x, lane = tid & 31, wm = tid >> 5;

    int g   = lane >> 3;
    int lr  = (lane & 7) + ((g & 1) << 3);
    int lcA = (g >> 1) << 3;
    int brn = (lane & 7) + ((g >> 1) << 3);
    int lcB = (g & 1) << 3;
    int cb  = (lane & 3) * 2;

    // load Q tile (64 x 128), already scaled
    for (int idx = tid; idx < 64*32; idx += 128) {
        int i = idx >> 5, dq = (idx & 31) * 4;
        float4 v = *(const float4*)(g_qsrt + (((size_t)(m*E_ + q0 + i)*QH_ + h) << 7) + dq);
        uint2 hi, lo;
        cvt4(v, hi, lo);
        *(uint2*)&as[AQH0 + i*136 + dq] = hi;
        *(uint2*)&as[AQL0 + i*136 + dq] = lo;
    }

    float Oa[16][4];
#pragma unroll
    for (int nt = 0; nt < 16; nt++)
#pragma unroll
        for (int c = 0; c < 4; c++) Oa[nt][c] = 0.f;
    float mrow[2] = {-INFINITY, -INFINITY};
    float lrow[2] = {0.f, 0.f};

    for (int kt = 0; kt < L; kt += 64) {
        __syncthreads();   // prior reads of K/V done (first iter: Q store fence too via this)
        // K tile (64 seq x 128 d)
        for (int idx = tid; idx < 64*32; idx += 128) {
            int j = idx >> 5, dq = (idx & 31) * 4;
            float4 v = *(const float4*)(g_ksrt + (((size_t)(m*E_ + kt + j)) << 7) + dq);
            uint2 hi, lo;
            cvt4(v, hi, lo);
            *(uint2*)&as[AKH0 + j*136 + dq] = hi;
            *(uint2*)&as[AKL0 + j*136 + dq] = lo;
        }
        // V^T tile (128 d x 64 seq)
        for (int idx = tid; idx < 128*16; idx += 128) {
            int d = idx >> 4, jq = (idx & 15) * 4;
            float4 v = *(const float4*)(g_vsrtT + ((size_t)(m*D_ + d))*E_ + kt + jq);
            uint2 hi, lo;
            cvt4(v, hi, lo);
            *(uint2*)&as[AVH0 + d*72 + jq] = hi;
            *(uint2*)&as[AVL0 + d*72 + jq] = lo;
        }
        __syncthreads();

        // S = Q K^T (16 rows per warp x 64 cols)
        float Sacc[8][4];
#pragma unroll
        for (int nt = 0; nt < 8; nt++)
#pragma unroll
            for (int c = 0; c < 4; c++) Sacc[nt][c] = 0.f;
#pragma unroll
        for (int kc = 0; kc < 8; kc++) {
            uint32_t qh[4], ql[4];
            ldsm4(qh, &as[AQH0 + (wm*16 + lr)*136 + kc*16 + lcA]);
            ldsm4(ql, &as[AQL0 + (wm*16 + lr)*136 + kc*16 + lcA]);
#pragma unroll
            for (int nt2 = 0; nt2 < 4; nt2++) {
                uint32_t bh[4], bl[4];
                ldsm4(bh, &as[AKH0 + (nt2*16 + brn)*136 + kc*16 + lcB]);
                ldsm4(bl, &as[AKL0 + (nt2*16 + brn)*136 + kc*16 + lcB]);
                mma16816(Sacc[2*nt2],   qh, bh[0], bh[1]);
                mma16816(Sacc[2*nt2],   qh, bl[0], bl[1]);
                mma16816(Sacc[2*nt2],   ql, bh[0], bh[1]);
                mma16816(Sacc[2*nt2+1], qh, bh[2], bh[3]);
                mma16816(Sacc[2*nt2+1], qh, bl[2], bl[3]);
                mma16816(Sacc[2*nt2+1], ql, bh[2], bh[3]);
            }
        }

        // online softmax (Q already scaled)
        int lim = L - kt;
#pragma unroll
        for (int nt = 0; nt < 8; nt++) {
            int c0 = nt*8 + cb;
            if (c0     >= lim) { Sacc[nt][0] = -1e30f; Sacc[nt][2] = -1e30f; }
            if (c0 + 1 >= lim) { Sacc[nt][1] = -1e30f; Sacc[nt][3] = -1e30f; }
        }
#pragma unroll
        for (int rr = 0; rr < 2; rr++) {
            float mx = -INFINITY;
#pragma unroll
            for (int nt = 0; nt < 8; nt++)
                mx = fmaxf(mx, fmaxf(Sacc[nt][rr*2], Sacc[nt][rr*2+1]));
            mx = fmaxf(mx, __shfl_xor_sync(0xffffffffu, mx, 1));
            mx = fmaxf(mx, __shfl_xor_sync(0xffffffffu, mx, 2));
            float mn = fmaxf(mrow[rr], mx);
            float corr = __expf(mrow[rr] - mn);
            mrow[rr] = mn;
            float ps = 0.f;
#pragma unroll
            for (int nt = 0; nt < 8; nt++) {
                float p0 = __expf(Sacc[nt][rr*2]   - mn);
                float p1 = __expf(Sacc[nt][rr*2+1] - mn);
                Sacc[nt][rr*2] = p0; Sacc[nt][rr*2+1] = p1;
                ps += p0 + p1;
            }
            ps += __shfl_xor_sync(0xffffffffu, ps, 1);
            ps += __shfl_xor_sync(0xffffffffu, ps, 2);
            lrow[rr] = lrow[rr] * corr + ps;
#pragma unroll
            for (int nt = 0; nt < 16; nt++) {
                Oa[nt][rr*2]   *= corr;
                Oa[nt][rr*2+1] *= corr;
            }
        }

        // O += P V  (P fragments built straight from Sacc registers)
#pragma unroll
        for (int kc2 = 0; kc2 < 4; kc2++) {
            uint32_t pah[4], pal[4];
            packhl(Sacc[2*kc2][0],   Sacc[2*kc2][1],   pah[0], pal[0]);
            packhl(Sacc[2*kc2][2],   Sacc[2*kc2][3],   pah[1], pal[1]);
            packhl(Sacc[2*kc2+1][0], Sacc[2*kc2+1][1], pah[2], pal[2]);
            packhl(Sacc[2*kc2+1][2], Sacc[2*kc2+1][3], pah[3], pal[3]);
#pragma unroll
            for (int nt2 = 0; nt2 < 8; nt2++) {
                uint32_t vh[4], vl[4];
                ldsm4(vh, &as[AVH0 + (nt2*16 + brn)*72 + kc2*16 + lcB]);
                ldsm4(vl, &as[AVL0 + (nt2*16 + brn)*72 + kc2*16 + lcB]);
                mma16816(Oa[2*nt2],   pah, vh[0], vh[1]);
                mma16816(Oa[2*nt2],   pah, vl[0], vl[1]);
                mma16816(Oa[2*nt2],   pal, vh[0], vh[1]);
                mma16816(Oa[2*nt2+1], pah, vh[2], vh[3]);
                mma16816(Oa[2*nt2+1], pah, vl[2], vl[3]);
                mma16816(Oa[2*nt2+1], pal, vh[2], vh[3]);
            }
        }
    }

    // epilogue: scatter rows back to token order with kv_weight / l
#pragma unroll
    for (int rr = 0; rr < 2; rr++) {
        int row_local = wm*16 + (lane >> 2) + 8*rr;
        int gr = q0 + row_local;
        if (gr < L) {
            int e = g_list[m*E_ + gr];
            int t = e >> 2, a = e & 3;
            float w = g_kvw[t*A_ + a] / lrow[rr];
            float* base = g_ao + (size_t)t*(A_*QH_*D_) + (a*QH_ + h)*D_;
#pragma unroll
            for (int nt = 0; nt < 16; nt++) {
                int col = nt*8 + cb;
                *(float2*)(base + col) = make_float2(Oa[nt][rr*2]*w, Oa[nt][rr*2+1]*w);
            }
        }
    }
}

// ---------------- launch ----------------
extern "C" void kernel_launch(void* const* d_in, const int* in_sizes, int n_in,
                              void* d_out, int out_size)
{
    const float* x  = (const float*)d_in[0];
    const float* wq = (const float*)d_in[1];
    const float* wk = (const float*)d_in[2];
    const float* wv = (const float*)d_in[3];
    const float* wr = (const float*)d_in[4];
    const float* wo = (const float*)d_in[5];
    float* out = (float*)d_out;

    float *yq, *yk, *yv, *ao, *part;
    cudaGetSymbolAddress((void**)&yq, g_yq);
    cudaGetSymbolAddress((void**)&yk, g_yk);
    cudaGetSymbolAddress((void**)&yv, g_yv);
    cudaGetSymbolAddress((void**)&ao, g_ao);
    cudaGetSymbolAddress((void**)&part, g_part);

    cudaFuncSetAttribute(gemm3seg,  cudaFuncAttributeMaxDynamicSharedMemorySize, 2*4*128*40*2);
    cudaFuncSetAttribute(attn_kernel, cudaFuncAttributeMaxDynamicSharedMemorySize, ATTN_SMEM_BYTES);

    router_kernel<<<S_/4, 128>>>(x, wr);
    build_lists_kernel<<<1, 192>>>();
    aux_reduce_kernel<<<1, 256>>>(out, out_size);

    // fused Q/K/V projections
    gemm3seg<<<dim3(24, 8, 1), 256, 2*4*128*40*2>>>(x, wq, wk, wv, yq, yk, yv,
                                                    EMB_, 12, 6, M_*QH_*D_, M_*D_, M_*D_);

    gather_rope_kernel<<<E_, 128>>>();
    attn_kernel<<<dim3(E_/64, QH_, M_), 128, ATTN_SMEM_BYTES>>>();

    // output projection, split-K=2 into partials, then sum
    gemm3seg<<<dim3(8, 8, 2), 256, 2*4*128*40*2>>>(ao, wo, nullptr, nullptr, part, nullptr, nullptr,
                                                   EMB_, 8, 0, EMB_, 0, 0);
    add_out_kernel<<<S_*EMB_/256, 256>>>(out);
}